// round 2
// baseline (speedup 1.0000x reference)
#include <cuda_runtime.h>

#define BB 4
#define DD 256
#define NN 4096
#define MM 4096

#define TILE_N 128
#define TILE_M 128
#define KC 64
#define NKC (DD / KC)     // 4 k-chunks
#define NMT (MM / TILE_M) // 32 m-tiles
#define THREADS 256

#define SMEM_AS_FLOATS (DD * TILE_N)      // 32768 (A tile, persistent, pre-scaled by 2)
#define SMEM_BS_FLOATS (2 * KC * TILE_M)  // 16384 (B chunk, double buffered)
#define SMEM_YY_FLOATS (TILE_M)           // 128
#define SMEM_TG_FLOATS (3 * TILE_M)       // 384
#define SMEM_TOTAL_BYTES ((SMEM_AS_FLOATS + SMEM_BS_FLOATS + SMEM_YY_FLOATS + SMEM_TG_FLOATS) * 4)

// scratch: yy[b][m] = sum_d tgt_emb[b,d,m]^2
__device__ float g_yy[BB * MM];

__global__ void yy_kernel(const float* __restrict__ tgt_emb) {
    int b = blockIdx.y;
    int m = blockIdx.x * blockDim.x + threadIdx.x;
    const float* p = tgt_emb + b * DD * MM + m;
    float s = 0.f;
#pragma unroll 8
    for (int d = 0; d < DD; ++d) {
        float v = p[d * MM];
        s += v * v;
    }
    g_yy[b * MM + m] = s;
}

__device__ __forceinline__ unsigned long long pack2(float lo, float hi) {
    unsigned long long r;
    asm("mov.b64 %0, {%1, %2};" : "=l"(r)
        : "r"(__float_as_uint(lo)), "r"(__float_as_uint(hi)));
    return r;
}

__device__ __forceinline__ void unpack2(unsigned long long v, float& lo, float& hi) {
    unsigned a, b;
    asm("mov.b64 {%0, %1}, %2;" : "=r"(a), "=r"(b) : "l"(v));
    lo = __uint_as_float(a);
    hi = __uint_as_float(b);
}

// packed dual-FMA: d.lo = a.lo*b.lo + c.lo ; d.hi = a.hi*b.hi + c.hi
#define FMA2(d, a, b, c) \
    asm("fma.rn.f32x2 %0, %1, %2, %3;" : "=l"(d) : "l"(a), "l"(b), "l"(c))

__global__ void __launch_bounds__(THREADS, 1)
corr_kernel(const float* __restrict__ src_emb,
            const float* __restrict__ tgt_emb,
            const float* __restrict__ tgt,
            float* __restrict__ out) {
    extern __shared__ float smem[];
    float* As   = smem;                      // [DD][TILE_N], holds 2*src_emb
    float* Bs   = As + SMEM_AS_FLOATS;       // [2][KC][TILE_M]
    float* yy_s = Bs + SMEM_BS_FLOATS;       // [TILE_M]
    float* tg_s = yy_s + SMEM_YY_FLOATS;     // [3][TILE_M]

    const int tid = threadIdx.x;
    const int tx  = tid & 15;   // m direction (16 lanes, columns interleaved stride 16)
    const int ty  = tid >> 4;   // n direction (16 groups of 8 adjacent rows)
    const int b   = blockIdx.y;
    const int n0  = blockIdx.x * TILE_N;

    // ---- Load persistent A tile: As[d][n] = 2 * src_emb[b][d][n0+n] ----
    {
        const float4* g = (const float4*)(src_emb + b * DD * NN);
#pragma unroll
        for (int i = 0; i < (DD * TILE_N / 4) / THREADS; ++i) {
            int e = tid + i * THREADS;
            int f = e * 4;
            int d = f / TILE_N;
            int c = f % TILE_N;
            float4 v = g[(d * NN + n0 + c) >> 2];
            v.x *= 2.f; v.y *= 2.f; v.z *= 2.f; v.w *= 2.f;
            *(float4*)(As + d * TILE_N + c) = v;
        }
    }

    // per-row online-softmax state (rows n0 + ty*8 + r)
    float rmax[8], rsum[8], o0[8], o1[8], o2[8];
#pragma unroll
    for (int r = 0; r < 8; ++r) {
        rmax[r] = -1e30f; rsum[r] = 0.f;
        o0[r] = 0.f; o1[r] = 0.f; o2[r] = 0.f;
    }

    const float4* gB = (const float4*)(tgt_emb + b * DD * MM);

    for (int mt = 0; mt < NMT; ++mt) {
        const int m0 = mt * TILE_M;
        __syncthreads();  // previous tile's smem readers done

        // yy + tgt values for this m tile (512 floats)
        for (int e = tid; e < 4 * TILE_M; e += THREADS) {
            if (e < TILE_M) {
                yy_s[e] = g_yy[b * MM + m0 + e];
            } else {
                int q = e - TILE_M;
                int c = q / TILE_M;
                int mm = q % TILE_M;
                tg_s[c * TILE_M + mm] = tgt[b * 3 * MM + c * MM + m0 + mm];
            }
        }
        // B chunk 0
#pragma unroll
        for (int i = 0; i < 8; ++i) {
            int e = tid + i * THREADS;
            int f = e * 4;
            int k = f / TILE_M;
            int c = f % TILE_M;
            *(float4*)(Bs + k * TILE_M + c) = gB[(k * MM + m0 + c) >> 2];
        }
        __syncthreads();

        unsigned long long acc[4][8];
#pragma unroll
        for (int p = 0; p < 4; ++p)
#pragma unroll
            for (int jj = 0; jj < 8; ++jj) acc[p][jj] = 0ull;

        int cur = 0;
        for (int kc = 0; kc < NKC; ++kc) {
            // prefetch next chunk into registers
            float4 pf[8];
            if (kc + 1 < NKC) {
#pragma unroll
                for (int i = 0; i < 8; ++i) {
                    int e = tid + i * THREADS;
                    int f = e * 4;
                    int k = f / TILE_M;
                    int c = f % TILE_M;
                    pf[i] = gB[(((kc + 1) * KC + k) * MM + m0 + c) >> 2];
                }
            }
            // main register GEMM on this chunk
            const float* arow = As + (kc * KC) * TILE_N + ty * 8;
            const float* brow = Bs + cur * (KC * TILE_M) + tx;
#pragma unroll 8
            for (int k = 0; k < KC; ++k) {
                unsigned long long a2[4];
#pragma unroll
                for (int p = 0; p < 4; ++p)
                    a2[p] = *(const unsigned long long*)(arow + 2 * p);
                unsigned long long b2[8];
#pragma unroll
                for (int jj = 0; jj < 8; ++jj) {
                    float bv = brow[16 * jj];
                    b2[jj] = pack2(bv, bv);
                }
#pragma unroll
                for (int p = 0; p < 4; ++p)
#pragma unroll
                    for (int jj = 0; jj < 8; ++jj)
                        FMA2(acc[p][jj], a2[p], b2[jj], acc[p][jj]);
                arow += TILE_N;
                brow += TILE_M;
            }
            if (kc + 1 < NKC) {
                __syncthreads();
#pragma unroll
                for (int i = 0; i < 8; ++i) {
                    int e = tid + i * THREADS;
                    int f = e * 4;
                    int k = f / TILE_M;
                    int c = f % TILE_M;
                    *(float4*)(Bs + (cur ^ 1) * (KC * TILE_M) + k * TILE_M + c) = pf[i];
                }
                __syncthreads();
                cur ^= 1;
            }
        }

        // ---- epilogue: logits = acc - yy ; online softmax over m ----
        float yyv[8], tv0[8], tv1[8], tv2[8];
#pragma unroll
        for (int jj = 0; jj < 8; ++jj) {
            int mcol = tx + 16 * jj;
            yyv[jj] = yy_s[mcol];
            tv0[jj] = tg_s[mcol];
            tv1[jj] = tg_s[TILE_M + mcol];
            tv2[jj] = tg_s[2 * TILE_M + mcol];
        }

        auto do_row = [&](float (&lg)[8], int r) {
            float tmax = lg[0];
#pragma unroll
            for (int jj = 1; jj < 8; ++jj) tmax = fmaxf(tmax, lg[jj]);
#pragma unroll
            for (int off = 8; off >= 1; off >>= 1)
                tmax = fmaxf(tmax, __shfl_xor_sync(0xffffffffu, tmax, off, 16));
            float nm = fmaxf(rmax[r], tmax);
            float corr = __expf(rmax[r] - nm);
            rmax[r] = nm;
            float ls = 0.f, a0 = 0.f, a1 = 0.f, a2 = 0.f;
#pragma unroll
            for (int jj = 0; jj < 8; ++jj) {
                float pj = __expf(lg[jj] - nm);
                ls += pj;
                a0 += pj * tv0[jj];
                a1 += pj * tv1[jj];
                a2 += pj * tv2[jj];
            }
#pragma unroll
            for (int off = 8; off >= 1; off >>= 1)
                ls += __shfl_xor_sync(0xffffffffu, ls, off, 16);
            rsum[r] = rsum[r] * corr + ls;
            o0[r] = o0[r] * corr + a0;
            o1[r] = o1[r] * corr + a1;
            o2[r] = o2[r] * corr + a2;
        };

#pragma unroll
        for (int p = 0; p < 4; ++p) {
            float lgA[8], lgB[8];
#pragma unroll
            for (int jj = 0; jj < 8; ++jj) {
                float lo, hi;
                unpack2(acc[p][jj], lo, hi);
                lgA[jj] = lo - yyv[jj];
                lgB[jj] = hi - yyv[jj];
            }
            do_row(lgA, 2 * p);
            do_row(lgB, 2 * p + 1);
        }
    }

    // ---- final: reduce partial o across the 16 m-lanes, write out ----
#pragma unroll
    for (int r = 0; r < 8; ++r) {
        float v0 = o0[r], v1 = o1[r], v2 = o2[r];
#pragma unroll
        for (int off = 8; off >= 1; off >>= 1) {
            v0 += __shfl_xor_sync(0xffffffffu, v0, off, 16);
            v1 += __shfl_xor_sync(0xffffffffu, v1, off, 16);
            v2 += __shfl_xor_sync(0xffffffffu, v2, off, 16);
        }
        if (tx == 0) {
            int n = n0 + ty * 8 + r;
            float inv = 1.f / rsum[r];
            out[b * 3 * NN + n]          = v0 * inv;
            out[b * 3 * NN + NN + n]     = v1 * inv;
            out[b * 3 * NN + 2 * NN + n] = v2 * inv;
        }
    }
}

extern "C" void kernel_launch(void* const* d_in, const int* in_sizes, int n_in,
                              void* d_out, int out_size) {
    // inputs per metadata: [0]=src (unused), [1]=tgt, [2]=src_emb, [3]=tgt_emb
    const float* tgt     = (const float*)d_in[1];
    const float* src_emb = (const float*)d_in[2];
    const float* tgt_emb = (const float*)d_in[3];
    float* out = (float*)d_out;

    cudaFuncSetAttribute(corr_kernel,
                         cudaFuncAttributeMaxDynamicSharedMemorySize,
                         SMEM_TOTAL_BYTES);

    yy_kernel<<<dim3(MM / THREADS, BB), THREADS>>>(tgt_emb);
    corr_kernel<<<dim3(NN / TILE_N, BB), THREADS, SMEM_TOTAL_BYTES>>>(
        src_emb, tgt_emb, tgt, out);
}

// round 4
// speedup vs baseline: 2.3480x; 2.3480x over previous
#include <cuda_runtime.h>
#include <cuda_bf16.h>
#include <cstdint>

#define BB 4
#define DD 256
#define NN 4096
#define MM 4096
#define TN 128            // n rows per CTA
#define TM 32             // m cols per tile
#define NMT (MM / TM)     // 128 m-tiles
#define L2E 1.4426950408889634f

#define ROW_ELEMS 264     // 256 + 8 pad -> 528B row stride (conflict-free)
#define ROW_BYTES (ROW_ELEMS * 2)
#define B_HALF (TM * ROW_BYTES)          // 16896
#define B_BLOB (2 * B_HALF)              // 33792 (hi then lo)
#define A_HALF (TN * ROW_BYTES)          // 67584

__device__ __align__(16) unsigned char g_B[BB * NMT * B_BLOB];  // ~16.5MB
__device__ __align__(16) float4 g_ytg[BB * MM];                 // (yy*log2e, t0,t1,t2)

// ---------------- helpers ----------------
__device__ __forceinline__ uint32_t smem_u32(const void* p) {
    uint32_t a;
    asm("{ .reg .u64 t; cvta.to.shared.u64 t, %1; cvt.u32.u64 %0, t; }"
        : "=r"(a) : "l"(p));
    return a;
}

#define MBARRIER_INIT(mbar, cnt) \
    asm volatile("mbarrier.init.shared.b64 [%0], %1;" \
                 :: "r"((uint32_t)(mbar)), "r"((uint32_t)(cnt)) : "memory")
#define MBARRIER_EXPECT_TX(mbar, bytes) \
    asm volatile("mbarrier.arrive.expect_tx.shared.b64 _, [%0], %1;" \
                 :: "r"((uint32_t)(mbar)), "r"((uint32_t)(bytes)) : "memory")
#define MBARRIER_WAIT_PARITY(mbar, ph) do {                                    \
    uint32_t _m = (uint32_t)(mbar); uint32_t _p = (uint32_t)(ph);               \
    asm volatile(                                                               \
        "{\n\t.reg .pred P1;\n\t"                                               \
        "WL_%=:\n\t"                                                            \
        "mbarrier.try_wait.parity.acquire.cta.shared::cta.b64 P1, [%0], %1, 0x989680;\n\t" \
        "@P1 bra.uni WD_%=;\n\t"                                                \
        "bra.uni WL_%=;\n\t"                                                    \
        "WD_%=:\n\t}"                                                           \
        :: "r"(_m), "r"(_p) : "memory");                                        \
} while (0)

__device__ __forceinline__ void bulk_g2s(uint32_t dst_smem, const void* src,
                                         uint32_t bytes, uint32_t mbar) {
    asm volatile(
        "cp.async.bulk.shared::cluster.global.mbarrier::complete_tx::bytes [%0], [%1], %2, [%3];"
        :: "r"(dst_smem), "l"(src), "r"(bytes), "r"(mbar) : "memory");
}

__device__ __forceinline__ float ex2(float x) {
    float r;
    asm("ex2.approx.f32 %0, %1;" : "=f"(r) : "f"(x));
    return r;
}

__device__ __forceinline__ void mma_bf16(float (&c)[4],
                                         uint32_t a0, uint32_t a1, uint32_t a2, uint32_t a3,
                                         uint32_t b0, uint32_t b1) {
    asm volatile(
        "mma.sync.aligned.m16n8k16.row.col.f32.bf16.bf16.f32 "
        "{%0,%1,%2,%3}, {%4,%5,%6,%7}, {%8,%9}, {%0,%1,%2,%3};"
        : "+f"(c[0]), "+f"(c[1]), "+f"(c[2]), "+f"(c[3])
        : "r"(a0), "r"(a1), "r"(a2), "r"(a3), "r"(b0), "r"(b1));
}

__device__ __forceinline__ void split_pair(float f0, float f1,
                                           uint32_t& hi, uint32_t& lo) {
    __nv_bfloat16 h0 = __float2bfloat16(f0);
    __nv_bfloat16 h1 = __float2bfloat16(f1);
    __nv_bfloat16 l0 = __float2bfloat16(f0 - __bfloat162float(h0));
    __nv_bfloat16 l1 = __float2bfloat16(f1 - __bfloat162float(h1));
    hi = (uint32_t)__bfloat16_as_ushort(h0) | ((uint32_t)__bfloat16_as_ushort(h1) << 16);
    lo = (uint32_t)__bfloat16_as_ushort(l0) | ((uint32_t)__bfloat16_as_ushort(l1) << 16);
}

// ======= Kernel 1: tgt_emb -> padded bf16 hi/lo blobs (SMEM image) + ytg =======
#define CV_PAD 264
#define CONVB_SMEM ((TM * CV_PAD + TM) * 4)

__global__ void __launch_bounds__(256)
convB_kernel(const float* __restrict__ tgt_emb, const float* __restrict__ tgt) {
    extern __shared__ float cs[];          // [TM][CV_PAD] transpose stage
    float* syy = cs + TM * CV_PAD;
    const int tid = threadIdx.x;
    const int b = blockIdx.y, mt = blockIdx.x, m0 = mt * TM;

    if (tid < TM) syy[tid] = 0.f;
    __syncthreads();

    const float* g = tgt_emb + (size_t)b * DD * MM + m0;
    for (int i = tid; i < DD * TM; i += 256) {
        int d = i >> 5, m = i & 31;
        cs[m * CV_PAD + d] = g[(size_t)d * MM + m];
    }
    __syncthreads();

    unsigned char* outh = g_B + (size_t)(b * NMT + mt) * B_BLOB;
    unsigned char* outl = outh + B_HALF;

    for (int i = tid; i < TM * 32; i += 256) {   // task = (m-row, 8-wide k group)
        int m = i >> 5, kg = i & 31;
        const float* p = cs + m * CV_PAD + kg * 8;
        float4 v0 = *(const float4*)(p);
        float4 v1 = *(const float4*)(p + 4);
        float part = v0.x * v0.x + v0.y * v0.y + v0.z * v0.z + v0.w * v0.w
                   + v1.x * v1.x + v1.y * v1.y + v1.z * v1.z + v1.w * v1.w;
        atomicAdd(&syy[m], part);

        uint4 hq, lq;
        split_pair(v0.x, v0.y, hq.x, lq.x);
        split_pair(v0.z, v0.w, hq.y, lq.y);
        split_pair(v1.x, v1.y, hq.z, lq.z);
        split_pair(v1.z, v1.w, hq.w, lq.w);

        int byte = m * ROW_BYTES + kg * 16;
        *(uint4*)(outh + byte) = hq;
        *(uint4*)(outl + byte) = lq;
    }
    __syncthreads();
    if (tid < TM) {
        int m = m0 + tid;
        float4 v;
        v.x = L2E * syy[tid];
        v.y = tgt[(size_t)b * 3 * MM + m];
        v.z = tgt[(size_t)b * 3 * MM + MM + m];
        v.w = tgt[(size_t)b * 3 * MM + 2 * MM + m];
        g_ytg[b * MM + m] = v;
    }
}

// ======= Kernel 2: fused HMMA GEMM + per-thread online softmax =======
// SMEM: mbar[2]@0, ytg 2x512B @64, A_hi @1152, A_lo, B blobs (2 bufs)
#define SM_YTG 64
#define SM_A   1152
#define SM_B   (SM_A + 2 * A_HALF)              // 136320
#define SMEM_MAIN (SM_B + 2 * B_BLOB)           // 203904

struct RowState { float m, s, o0, o1, o2; };

__device__ __forceinline__ void row_update(RowState& st, const float (&lg)[8],
                                           const float4 (&yt)[8]) {
    float tmax = lg[0];
#pragma unroll
    for (int j = 1; j < 8; ++j) tmax = fmaxf(tmax, lg[j]);
    float nm = fmaxf(st.m, tmax);
    float corr = ex2(st.m - nm);
    st.m = nm;
    float ls = 0.f, a0 = 0.f, a1 = 0.f, a2 = 0.f;
#pragma unroll
    for (int j = 0; j < 8; ++j) {
        float p = ex2(lg[j] - nm);
        ls += p;
        a0 += p * yt[j].y;
        a1 += p * yt[j].z;
        a2 += p * yt[j].w;
    }
    st.s = st.s * corr + ls;
    st.o0 = st.o0 * corr + a0;
    st.o1 = st.o1 * corr + a1;
    st.o2 = st.o2 * corr + a2;
}

__device__ __forceinline__ void row_merge(RowState& st, int off) {
    float om = __shfl_xor_sync(0xffffffffu, st.m, off);
    float os = __shfl_xor_sync(0xffffffffu, st.s, off);
    float g0 = __shfl_xor_sync(0xffffffffu, st.o0, off);
    float g1 = __shfl_xor_sync(0xffffffffu, st.o1, off);
    float g2 = __shfl_xor_sync(0xffffffffu, st.o2, off);
    float nm = fmaxf(st.m, om);
    float ca = ex2(st.m - nm), cb = ex2(om - nm);
    st.m = nm;
    st.s = st.s * ca + os * cb;
    st.o0 = st.o0 * ca + g0 * cb;
    st.o1 = st.o1 * ca + g1 * cb;
    st.o2 = st.o2 * ca + g2 * cb;
}

__global__ void __launch_bounds__(256, 1)
corr_mma_kernel(const float* __restrict__ src_emb, float* __restrict__ out) {
    extern __shared__ __align__(16) unsigned char smraw[];
    const uint32_t sb = smem_u32(smraw);
    const int tid = threadIdx.x;
    const int wid = tid >> 5;
    const int lane = tid & 31;
    const int b = blockIdx.y;
    const int n0 = blockIdx.x * TN;

    if (tid == 0) {
        MBARRIER_INIT(sb + 0, 1);
        MBARRIER_INIT(sb + 8, 1);
    }
    __syncthreads();

    const unsigned char* gB = g_B + (size_t)b * NMT * B_BLOB;
    const float4* gY = g_ytg + b * MM;

    // kick off loads for tiles 0 and 1
    if (tid == 0) {
        MBARRIER_EXPECT_TX(sb + 0, B_BLOB + 512);
        bulk_g2s(sb + SM_B, gB, B_BLOB, sb + 0);
        bulk_g2s(sb + SM_YTG, gY, 512, sb + 0);
        MBARRIER_EXPECT_TX(sb + 8, B_BLOB + 512);
        bulk_g2s(sb + SM_B + B_BLOB, gB + B_BLOB, B_BLOB, sb + 8);
        bulk_g2s(sb + SM_YTG + 512, gY + TM, 512, sb + 8);
    }

    // ---- convert A (src_emb rows n0..n0+127, scaled by 2*log2e) into SMEM ----
    {
        unsigned char* Ah = smraw + SM_A;
        unsigned char* Al = Ah + A_HALF;
        const float* gA = src_emb + (size_t)b * DD * NN + n0;
        const float sc = 2.0f * L2E;
        for (int i = tid; i < DD * TN / 2; i += 256) {
            int n = i & 127;
            int dp = i >> 7;             // 0..127, covers d = 2dp, 2dp+1
            float v0 = sc * gA[(size_t)(2 * dp) * NN + n];
            float v1 = sc * gA[(size_t)(2 * dp + 1) * NN + n];
            uint32_t hi, lo;
            split_pair(v0, v1, hi, lo);
            *(uint32_t*)(Ah + n * ROW_BYTES + dp * 4) = hi;
            *(uint32_t*)(Al + n * ROW_BYTES + dp * 4) = lo;
        }
    }
    __syncthreads();

    // fragment base offsets
    const int q = lane & 3;
    const int r = lane >> 2;
    const uint32_t aoff = (wid * 16 + r) * ROW_BYTES + q * 4;
    const uint32_t boff = r * ROW_BYTES + q * 4;

    RowState st0 = {-1e30f, 0.f, 0.f, 0.f, 0.f};
    RowState st1 = {-1e30f, 0.f, 0.f, 0.f, 0.f};

    const unsigned char* Ah = smraw + SM_A;
    const unsigned char* Al = Ah + A_HALF;
    const float4* ytg_s = (const float4*)(smraw + SM_YTG);

    for (int t = 0; t < NMT; ++t) {
        const int buf = t & 1;
        MBARRIER_WAIT_PARITY(sb + 8 * buf, (t >> 1) & 1);

        const unsigned char* Bh = smraw + SM_B + buf * B_BLOB;
        const unsigned char* Bl = Bh + B_HALF;

        float acc[4][4];
#pragma unroll
        for (int j = 0; j < 4; ++j)
#pragma unroll
            for (int e = 0; e < 4; ++e) acc[j][e] = 0.f;

#pragma unroll
        for (int s = 0; s < 16; ++s) {
            const uint32_t k2 = s * 32;
            uint32_t ah0 = *(const uint32_t*)(Ah + aoff + k2);
            uint32_t ah1 = *(const uint32_t*)(Ah + aoff + k2 + 8 * ROW_BYTES);
            uint32_t ah2 = *(const uint32_t*)(Ah + aoff + k2 + 16);
            uint32_t ah3 = *(const uint32_t*)(Ah + aoff + k2 + 8 * ROW_BYTES + 16);
            uint32_t al0 = *(const uint32_t*)(Al + aoff + k2);
            uint32_t al1 = *(const uint32_t*)(Al + aoff + k2 + 8 * ROW_BYTES);
            uint32_t al2 = *(const uint32_t*)(Al + aoff + k2 + 16);
            uint32_t al3 = *(const uint32_t*)(Al + aoff + k2 + 8 * ROW_BYTES + 16);
#pragma unroll
            for (int j = 0; j < 4; ++j) {
                const uint32_t bj = boff + j * 8 * ROW_BYTES + k2;
                uint32_t bh0 = *(const uint32_t*)(Bh + bj);
                uint32_t bh1 = *(const uint32_t*)(Bh + bj + 16);
                uint32_t bl0 = *(const uint32_t*)(Bl + bj);
                uint32_t bl1 = *(const uint32_t*)(Bl + bj + 16);
                mma_bf16(acc[j], ah0, ah1, ah2, ah3, bh0, bh1);
                mma_bf16(acc[j], al0, al1, al2, al3, bh0, bh1);
                mma_bf16(acc[j], ah0, ah1, ah2, ah3, bl0, bl1);
            }
        }

        // grab this tile's (yy, t0..t2) for my 8 cols before buffer reuse
        float4 yt[8];
#pragma unroll
        for (int j = 0; j < 4; ++j)
#pragma unroll
            for (int e = 0; e < 2; ++e)
                yt[j * 2 + e] = ytg_s[buf * 32 + j * 8 + q * 2 + e];

        __syncthreads();   // everyone done with buf
        if (tid == 0 && t + 2 < NMT) {
            MBARRIER_EXPECT_TX(sb + 8 * buf, B_BLOB + 512);
            bulk_g2s(sb + SM_B + buf * B_BLOB, gB + (size_t)(t + 2) * B_BLOB,
                     B_BLOB, sb + 8 * buf);
            bulk_g2s(sb + SM_YTG + buf * 512, gY + (t + 2) * TM, 512, sb + 8 * buf);
        }

        // ---- per-thread online softmax (rows r0 = wid*16+r, r1 = +8) ----
        float l0[8], l1[8];
#pragma unroll
        for (int j = 0; j < 4; ++j)
#pragma unroll
            for (int e = 0; e < 2; ++e) {
                float yy = yt[j * 2 + e].x;
                l0[j * 2 + e] = acc[j][e] - yy;
                l1[j * 2 + e] = acc[j][2 + e] - yy;
            }
        row_update(st0, l0, yt);
        row_update(st1, l1, yt);
    }

    // ---- merge across quad (lanes sharing the same rows), write out ----
    row_merge(st0, 1); row_merge(st0, 2);
    row_merge(st1, 1); row_merge(st1, 2);

    if (q == 0) {
        size_t base = (size_t)b * 3 * NN;
        int na = n0 + wid * 16 + r;
        int nb = na + 8;
        float ia = 1.f / st0.s, ib = 1.f / st1.s;
        out[base + na] = st0.o0 * ia;
        out[base + NN + na] = st0.o1 * ia;
        out[base + 2 * NN + na] = st0.o2 * ia;
        out[base + nb] = st1.o0 * ib;
        out[base + NN + nb] = st1.o1 * ib;
        out[base + 2 * NN + nb] = st1.o2 * ib;
    }
}

extern "C" void kernel_launch(void* const* d_in, const int* in_sizes, int n_in,
                              void* d_out, int out_size) {
    // inputs per metadata: [0]=src (unused), [1]=tgt, [2]=src_emb, [3]=tgt_emb
    const float* tgt     = (const float*)d_in[1];
    const float* src_emb = (const float*)d_in[2];
    const float* tgt_emb = (const float*)d_in[3];
    float* out = (float*)d_out;

    cudaFuncSetAttribute(convB_kernel,
                         cudaFuncAttributeMaxDynamicSharedMemorySize, CONVB_SMEM);
    cudaFuncSetAttribute(corr_mma_kernel,
                         cudaFuncAttributeMaxDynamicSharedMemorySize, SMEM_MAIN);

    convB_kernel<<<dim3(NMT, BB), 256, CONVB_SMEM>>>(tgt_emb, tgt);
    corr_mma_kernel<<<dim3(NN / TN, BB), 256, SMEM_MAIN>>>(src_emb, out);
}

// round 5
// speedup vs baseline: 2.5623x; 1.0913x over previous
#include <cuda_runtime.h>
#include <cuda_bf16.h>
#include <cstdint>

#define BB 4
#define DD 256
#define NN 4096
#define MM 4096
#define TN 128            // n rows per CTA
#define TM 32             // m cols per tile
#define NMT (MM / TM)     // 128 m-tiles
#define L2E 1.4426950408889634f

#define ROW_ELEMS 264     // 256 + 8 pad -> 528B row stride (conflict-free)
#define ROW_BYTES (ROW_ELEMS * 2)
#define B_HALF (TM * ROW_BYTES)          // 16896
#define B_BLOB (2 * B_HALF)              // 33792 (hi then lo)
#define A_HALF (TN * ROW_BYTES)          // 67584

__device__ __align__(16) unsigned char g_B[BB * NMT * B_BLOB];  // ~16.5MB
__device__ __align__(16) float4 g_ytg[BB * MM];                 // (yy*log2e, t0,t1,t2)

// ---------------- helpers ----------------
__device__ __forceinline__ uint32_t smem_u32(const void* p) {
    uint32_t a;
    asm("{ .reg .u64 t; cvta.to.shared.u64 t, %1; cvt.u32.u64 %0, t; }"
        : "=r"(a) : "l"(p));
    return a;
}

#define MBARRIER_INIT(mbar, cnt) \
    asm volatile("mbarrier.init.shared.b64 [%0], %1;" \
                 :: "r"((uint32_t)(mbar)), "r"((uint32_t)(cnt)) : "memory")
#define MBARRIER_EXPECT_TX(mbar, bytes) \
    asm volatile("mbarrier.arrive.expect_tx.shared.b64 _, [%0], %1;" \
                 :: "r"((uint32_t)(mbar)), "r"((uint32_t)(bytes)) : "memory")
#define MBARRIER_WAIT_PARITY(mbar, ph) do {                                    \
    uint32_t _m = (uint32_t)(mbar); uint32_t _p = (uint32_t)(ph);               \
    asm volatile(                                                               \
        "{\n\t.reg .pred P1;\n\t"                                               \
        "WL_%=:\n\t"                                                            \
        "mbarrier.try_wait.parity.acquire.cta.shared::cta.b64 P1, [%0], %1, 0x989680;\n\t" \
        "@P1 bra.uni WD_%=;\n\t"                                                \
        "bra.uni WL_%=;\n\t"                                                    \
        "WD_%=:\n\t}"                                                           \
        :: "r"(_m), "r"(_p) : "memory");                                        \
} while (0)

__device__ __forceinline__ void bulk_g2s(uint32_t dst_smem, const void* src,
                                         uint32_t bytes, uint32_t mbar) {
    asm volatile(
        "cp.async.bulk.shared::cluster.global.mbarrier::complete_tx::bytes [%0], [%1], %2, [%3];"
        :: "r"(dst_smem), "l"(src), "r"(bytes), "r"(mbar) : "memory");
}

__device__ __forceinline__ float ex2(float x) {
    float r;
    asm("ex2.approx.f32 %0, %1;" : "=f"(r) : "f"(x));
    return r;
}

#define LDSM_X4(r, addr) \
    asm volatile("ldmatrix.sync.aligned.m8n8.x4.shared.b16 {%0,%1,%2,%3}, [%4];" \
                 : "=r"((r)[0]), "=r"((r)[1]), "=r"((r)[2]), "=r"((r)[3]) \
                 : "r"(addr))

__device__ __forceinline__ void mma_bf16(float (&c)[4],
                                         const uint32_t (&a)[4],
                                         uint32_t b0, uint32_t b1) {
    asm volatile(
        "mma.sync.aligned.m16n8k16.row.col.f32.bf16.bf16.f32 "
        "{%0,%1,%2,%3}, {%4,%5,%6,%7}, {%8,%9}, {%0,%1,%2,%3};"
        : "+f"(c[0]), "+f"(c[1]), "+f"(c[2]), "+f"(c[3])
        : "r"(a[0]), "r"(a[1]), "r"(a[2]), "r"(a[3]), "r"(b0), "r"(b1));
}

__device__ __forceinline__ void split_pair(float f0, float f1,
                                           uint32_t& hi, uint32_t& lo) {
    __nv_bfloat16 h0 = __float2bfloat16(f0);
    __nv_bfloat16 h1 = __float2bfloat16(f1);
    __nv_bfloat16 l0 = __float2bfloat16(f0 - __bfloat162float(h0));
    __nv_bfloat16 l1 = __float2bfloat16(f1 - __bfloat162float(h1));
    hi = (uint32_t)__bfloat16_as_ushort(h0) | ((uint32_t)__bfloat16_as_ushort(h1) << 16);
    lo = (uint32_t)__bfloat16_as_ushort(l0) | ((uint32_t)__bfloat16_as_ushort(l1) << 16);
}

// ======= Kernel 1: tgt_emb -> padded bf16 hi/lo blobs (SMEM image) + ytg =======
#define CV_PAD 264
#define CONVB_SMEM ((TM * CV_PAD + TM) * 4)

__global__ void __launch_bounds__(256)
convB_kernel(const float* __restrict__ tgt_emb, const float* __restrict__ tgt) {
    extern __shared__ float cs[];          // [TM][CV_PAD] transpose stage
    float* syy = cs + TM * CV_PAD;
    const int tid = threadIdx.x;
    const int b = blockIdx.y, mt = blockIdx.x, m0 = mt * TM;

    if (tid < TM) syy[tid] = 0.f;
    __syncthreads();

    const float* g = tgt_emb + (size_t)b * DD * MM + m0;
    for (int i = tid; i < DD * TM; i += 256) {
        int d = i >> 5, m = i & 31;
        cs[m * CV_PAD + d] = g[(size_t)d * MM + m];
    }
    __syncthreads();

    unsigned char* outh = g_B + (size_t)(b * NMT + mt) * B_BLOB;
    unsigned char* outl = outh + B_HALF;

    for (int i = tid; i < TM * 32; i += 256) {   // task = (m-row, 8-wide k group)
        int m = i >> 5, kg = i & 31;
        const float* p = cs + m * CV_PAD + kg * 8;
        float4 v0 = *(const float4*)(p);
        float4 v1 = *(const float4*)(p + 4);
        float part = v0.x * v0.x + v0.y * v0.y + v0.z * v0.z + v0.w * v0.w
                   + v1.x * v1.x + v1.y * v1.y + v1.z * v1.z + v1.w * v1.w;
        atomicAdd(&syy[m], part);

        uint4 hq, lq;
        split_pair(v0.x, v0.y, hq.x, lq.x);
        split_pair(v0.z, v0.w, hq.y, lq.y);
        split_pair(v1.x, v1.y, hq.z, lq.z);
        split_pair(v1.z, v1.w, hq.w, lq.w);

        int byte = m * ROW_BYTES + kg * 16;
        *(uint4*)(outh + byte) = hq;
        *(uint4*)(outl + byte) = lq;
    }
    __syncthreads();
    if (tid < TM) {
        int m = m0 + tid;
        float4 v;
        v.x = L2E * syy[tid];
        v.y = tgt[(size_t)b * 3 * MM + m];
        v.z = tgt[(size_t)b * 3 * MM + MM + m];
        v.w = tgt[(size_t)b * 3 * MM + 2 * MM + m];
        g_ytg[b * MM + m] = v;
    }
}

// ======= Kernel 2: fused HMMA GEMM (ldmatrix feed) + per-thread online softmax =======
// SMEM: mbar[2]@0, ytg 2x512B @64, A_hi @1152, A_lo, B blobs (2 bufs)
#define SM_YTG 64
#define SM_A   1152
#define SM_B   (SM_A + 2 * A_HALF)              // 136320
#define SMEM_MAIN (SM_B + 2 * B_BLOB)           // 203904

struct RowState { float m, s, o0, o1, o2; };

__device__ __forceinline__ void row_update(RowState& st, const float (&lg)[8],
                                           const float4 (&yt)[8]) {
    float tmax = lg[0];
#pragma unroll
    for (int j = 1; j < 8; ++j) tmax = fmaxf(tmax, lg[j]);
    float nm = fmaxf(st.m, tmax);
    float corr = ex2(st.m - nm);
    st.m = nm;
    float ls = 0.f, a0 = 0.f, a1 = 0.f, a2 = 0.f;
#pragma unroll
    for (int j = 0; j < 8; ++j) {
        float p = ex2(lg[j] - nm);
        ls += p;
        a0 += p * yt[j].y;
        a1 += p * yt[j].z;
        a2 += p * yt[j].w;
    }
    st.s = st.s * corr + ls;
    st.o0 = st.o0 * corr + a0;
    st.o1 = st.o1 * corr + a1;
    st.o2 = st.o2 * corr + a2;
}

__device__ __forceinline__ void row_merge(RowState& st, int off) {
    float om = __shfl_xor_sync(0xffffffffu, st.m, off);
    float os = __shfl_xor_sync(0xffffffffu, st.s, off);
    float g0 = __shfl_xor_sync(0xffffffffu, st.o0, off);
    float g1 = __shfl_xor_sync(0xffffffffu, st.o1, off);
    float g2 = __shfl_xor_sync(0xffffffffu, st.o2, off);
    float nm = fmaxf(st.m, om);
    float ca = ex2(st.m - nm), cb = ex2(om - nm);
    st.m = nm;
    st.s = st.s * ca + os * cb;
    st.o0 = st.o0 * ca + g0 * cb;
    st.o1 = st.o1 * ca + g1 * cb;
    st.o2 = st.o2 * ca + g2 * cb;
}

__global__ void __launch_bounds__(256, 1)
corr_mma_kernel(const float* __restrict__ src_emb, float* __restrict__ out) {
    extern __shared__ __align__(16) unsigned char smraw[];
    const uint32_t sb = smem_u32(smraw);
    const int tid = threadIdx.x;
    const int wid = tid >> 5;
    const int lane = tid & 31;
    const int b = blockIdx.y;
    const int n0 = blockIdx.x * TN;

    if (tid == 0) {
        MBARRIER_INIT(sb + 0, 1);
        MBARRIER_INIT(sb + 8, 1);
    }
    __syncthreads();

    const unsigned char* gB = g_B + (size_t)b * NMT * B_BLOB;
    const float4* gY = g_ytg + b * MM;

    // kick off loads for tiles 0 and 1
    if (tid == 0) {
        MBARRIER_EXPECT_TX(sb + 0, B_BLOB + 512);
        bulk_g2s(sb + SM_B, gB, B_BLOB, sb + 0);
        bulk_g2s(sb + SM_YTG, gY, 512, sb + 0);
        MBARRIER_EXPECT_TX(sb + 8, B_BLOB + 512);
        bulk_g2s(sb + SM_B + B_BLOB, gB + B_BLOB, B_BLOB, sb + 8);
        bulk_g2s(sb + SM_YTG + 512, gY + TM, 512, sb + 8);
    }

    // ---- convert A (src_emb rows n0..n0+127, scaled by 2*log2e) into SMEM ----
    {
        unsigned char* Ah = smraw + SM_A;
        unsigned char* Al = Ah + A_HALF;
        const float* gA = src_emb + (size_t)b * DD * NN + n0;
        const float sc = 2.0f * L2E;
        for (int i = tid; i < DD * TN / 2; i += 256) {
            int n = i & 127;
            int dp = i >> 7;             // 0..127, covers d = 2dp, 2dp+1
            float v0 = sc * gA[(size_t)(2 * dp) * NN + n];
            float v1 = sc * gA[(size_t)(2 * dp + 1) * NN + n];
            uint32_t hi, lo;
            split_pair(v0, v1, hi, lo);
            *(uint32_t*)(Ah + n * ROW_BYTES + dp * 4) = hi;
            *(uint32_t*)(Al + n * ROW_BYTES + dp * 4) = lo;
        }
    }
    __syncthreads();

    // ---- ldmatrix per-lane base addresses ----
    const int q = lane & 3;
    const int r = lane >> 2;
    // A x4: m0 rows w*16+0..7 (k+0), m1 rows +8 (k+0), m2 rows +0 (k+8), m3 rows +8 (k+8)
    const uint32_t rowA = wid * 16 + ((lane >> 3) & 1) * 8 + (lane & 7);
    const uint32_t aH = sb + SM_A + rowA * ROW_BYTES + (lane >> 4) * 16;
    const uint32_t aL = aH + A_HALF;
    // B x4 for j-pair jp: m0 rows jp*8 (k+0), m1 rows jp*8 (k+8), m2 rows (jp+1)*8 (k+0), m3 (k+8)
    const uint32_t bo0 = (uint32_t)(((0 + (lane >> 4)) * 8 + (lane & 7)) * ROW_BYTES
                                    + ((lane >> 3) & 1) * 16);
    const uint32_t bo2 = (uint32_t)(((2 + (lane >> 4)) * 8 + (lane & 7)) * ROW_BYTES
                                    + ((lane >> 3) & 1) * 16);

    RowState st0 = {-1e30f, 0.f, 0.f, 0.f, 0.f};
    RowState st1 = {-1e30f, 0.f, 0.f, 0.f, 0.f};

    const float4* ytg_s = (const float4*)(smraw + SM_YTG);

    for (int t = 0; t < NMT; ++t) {
        const int buf = t & 1;
        MBARRIER_WAIT_PARITY(sb + 8 * buf, (t >> 1) & 1);

        const uint32_t bb = sb + SM_B + buf * B_BLOB;

        float acc[4][4];
#pragma unroll
        for (int j = 0; j < 4; ++j)
#pragma unroll
            for (int e = 0; e < 4; ++e) acc[j][e] = 0.f;

#pragma unroll
        for (int s = 0; s < 16; ++s) {
            const uint32_t k2 = s * 32;
            uint32_t ah[4], al[4], bh[4], bh2[4], bl[4], bl2[4];
            LDSM_X4(ah, aH + k2);
            LDSM_X4(al, aL + k2);
            LDSM_X4(bh, bb + bo0 + k2);
            LDSM_X4(bh2, bb + bo2 + k2);
            LDSM_X4(bl, bb + B_HALF + bo0 + k2);
            LDSM_X4(bl2, bb + B_HALF + bo2 + k2);
            // hi*hi
            mma_bf16(acc[0], ah, bh[0], bh[1]);
            mma_bf16(acc[1], ah, bh[2], bh[3]);
            mma_bf16(acc[2], ah, bh2[0], bh2[1]);
            mma_bf16(acc[3], ah, bh2[2], bh2[3]);
            // lo*hi
            mma_bf16(acc[0], al, bh[0], bh[1]);
            mma_bf16(acc[1], al, bh[2], bh[3]);
            mma_bf16(acc[2], al, bh2[0], bh2[1]);
            mma_bf16(acc[3], al, bh2[2], bh2[3]);
            // hi*lo
            mma_bf16(acc[0], ah, bl[0], bl[1]);
            mma_bf16(acc[1], ah, bl[2], bl[3]);
            mma_bf16(acc[2], ah, bl2[0], bl2[1]);
            mma_bf16(acc[3], ah, bl2[2], bl2[3]);
        }

        // grab this tile's (yy, t0..t2) for my 8 cols before buffer reuse
        float4 yt[8];
#pragma unroll
        for (int j = 0; j < 4; ++j)
#pragma unroll
            for (int e = 0; e < 2; ++e)
                yt[j * 2 + e] = ytg_s[buf * 32 + j * 8 + q * 2 + e];

        __syncthreads();   // everyone done with buf
        if (tid == 0 && t + 2 < NMT) {
            MBARRIER_EXPECT_TX(sb + 8 * buf, B_BLOB + 512);
            bulk_g2s(sb + SM_B + buf * B_BLOB, gB + (size_t)(t + 2) * B_BLOB,
                     B_BLOB, sb + 8 * buf);
            bulk_g2s(sb + SM_YTG + buf * 512, gY + (t + 2) * TM, 512, sb + 8 * buf);
        }

        // ---- per-thread online softmax (rows r0 = wid*16+r, r1 = +8) ----
        float l0[8], l1[8];
#pragma unroll
        for (int j = 0; j < 4; ++j)
#pragma unroll
            for (int e = 0; e < 2; ++e) {
                float yy = yt[j * 2 + e].x;
                l0[j * 2 + e] = acc[j][e] - yy;
                l1[j * 2 + e] = acc[j][2 + e] - yy;
            }
        row_update(st0, l0, yt);
        row_update(st1, l1, yt);
    }

    // ---- merge across quad (lanes sharing the same rows), write out ----
    row_merge(st0, 1); row_merge(st0, 2);
    row_merge(st1, 1); row_merge(st1, 2);

    if (q == 0) {
        size_t base = (size_t)b * 3 * NN;
        int na = n0 + wid * 16 + r;
        int nb = na + 8;
        float ia = 1.f / st0.s, ib = 1.f / st1.s;
        out[base + na] = st0.o0 * ia;
        out[base + NN + na] = st0.o1 * ia;
        out[base + 2 * NN + na] = st0.o2 * ia;
        out[base + nb] = st1.o0 * ib;
        out[base + NN + nb] = st1.o1 * ib;
        out[base + 2 * NN + nb] = st1.o2 * ib;
    }
}

extern "C" void kernel_launch(void* const* d_in, const int* in_sizes, int n_in,
                              void* d_out, int out_size) {
    // inputs per metadata: [0]=src (unused), [1]=tgt, [2]=src_emb, [3]=tgt_emb
    const float* tgt     = (const float*)d_in[1];
    const float* src_emb = (const float*)d_in[2];
    const float* tgt_emb = (const float*)d_in[3];
    float* out = (float*)d_out;

    cudaFuncSetAttribute(convB_kernel,
                         cudaFuncAttributeMaxDynamicSharedMemorySize, CONVB_SMEM);
    cudaFuncSetAttribute(corr_mma_kernel,
                         cudaFuncAttributeMaxDynamicSharedMemorySize, SMEM_MAIN);

    convB_kernel<<<dim3(NMT, BB), 256, CONVB_SMEM>>>(tgt_emb, tgt);
    corr_mma_kernel<<<dim3(NN / TN, BB), 256, SMEM_MAIN>>>(src_emb, out);
}

// round 6
// speedup vs baseline: 2.6406x; 1.0306x over previous
#include <cuda_runtime.h>
#include <cuda_bf16.h>
#include <cstdint>

#define BB 4
#define DD 256
#define NN 4096
#define MM 4096
#define TN 128            // n rows per CTA
#define TM 32             // m cols per tile
#define NMT (MM / TM)     // 128 m-tiles
#define NSTAGE 3
#define L2E 1.4426950408889634f

#define ROW_BYTES 512     // 256 bf16, XOR-swizzled chunks (conflict-free for ldmatrix)
#define B_HALF (TM * ROW_BYTES)          // 16384
#define B_BLOB (2 * B_HALF)              // 32768 (hi then lo)
#define A_HALF (TN * ROW_BYTES)          // 65536

__device__ __align__(16) unsigned char g_B[BB * NMT * B_BLOB];  // 16MB
__device__ __align__(16) float4 g_ytg[BB * MM];                 // (yy*log2e, t0,t1,t2)

// ---------------- helpers ----------------
__device__ __forceinline__ uint32_t smem_u32(const void* p) {
    uint32_t a;
    asm("{ .reg .u64 t; cvta.to.shared.u64 t, %1; cvt.u32.u64 %0, t; }"
        : "=r"(a) : "l"(p));
    return a;
}

#define MBARRIER_INIT(mbar, cnt) \
    asm volatile("mbarrier.init.shared.b64 [%0], %1;" \
                 :: "r"((uint32_t)(mbar)), "r"((uint32_t)(cnt)) : "memory")
#define MBARRIER_EXPECT_TX(mbar, bytes) \
    asm volatile("mbarrier.arrive.expect_tx.shared.b64 _, [%0], %1;" \
                 :: "r"((uint32_t)(mbar)), "r"((uint32_t)(bytes)) : "memory")
#define MBARRIER_ARRIVE(mbar) \
    asm volatile("mbarrier.arrive.shared.b64 _, [%0];" \
                 :: "r"((uint32_t)(mbar)) : "memory")
#define MBARRIER_WAIT_PARITY(mbar, ph) do {                                    \
    uint32_t _m = (uint32_t)(mbar); uint32_t _p = (uint32_t)(ph);               \
    asm volatile(                                                               \
        "{\n\t.reg .pred P1;\n\t"                                               \
        "WL_%=:\n\t"                                                            \
        "mbarrier.try_wait.parity.acquire.cta.shared::cta.b64 P1, [%0], %1, 0x989680;\n\t" \
        "@P1 bra.uni WD_%=;\n\t"                                                \
        "bra.uni WL_%=;\n\t"                                                    \
        "WD_%=:\n\t}"                                                           \
        :: "r"(_m), "r"(_p) : "memory");                                        \
} while (0)

__device__ __forceinline__ void bulk_g2s(uint32_t dst_smem, const void* src,
                                         uint32_t bytes, uint32_t mbar) {
    asm volatile(
        "cp.async.bulk.shared::cluster.global.mbarrier::complete_tx::bytes [%0], [%1], %2, [%3];"
        :: "r"(dst_smem), "l"(src), "r"(bytes), "r"(mbar) : "memory");
}

__device__ __forceinline__ float ex2(float x) {
    float r;
    asm("ex2.approx.f32 %0, %1;" : "=f"(r) : "f"(x));
    return r;
}

#define LDSM_X4(r, addr) \
    asm volatile("ldmatrix.sync.aligned.m8n8.x4.shared.b16 {%0,%1,%2,%3}, [%4];" \
                 : "=r"((r)[0]), "=r"((r)[1]), "=r"((r)[2]), "=r"((r)[3]) \
                 : "r"(addr))

__device__ __forceinline__ void mma_bf16(float (&c)[4],
                                         const uint32_t (&a)[4],
                                         uint32_t b0, uint32_t b1) {
    asm volatile(
        "mma.sync.aligned.m16n8k16.row.col.f32.bf16.bf16.f32 "
        "{%0,%1,%2,%3}, {%4,%5,%6,%7}, {%8,%9}, {%0,%1,%2,%3};"
        : "+f"(c[0]), "+f"(c[1]), "+f"(c[2]), "+f"(c[3])
        : "r"(a[0]), "r"(a[1]), "r"(a[2]), "r"(a[3]), "r"(b0), "r"(b1));
}

__device__ __forceinline__ void split_pair(float f0, float f1,
                                           uint32_t& hi, uint32_t& lo) {
    __nv_bfloat16 h0 = __float2bfloat16(f0);
    __nv_bfloat16 h1 = __float2bfloat16(f1);
    __nv_bfloat16 l0 = __float2bfloat16(f0 - __bfloat162float(h0));
    __nv_bfloat16 l1 = __float2bfloat16(f1 - __bfloat162float(h1));
    hi = (uint32_t)__bfloat16_as_ushort(h0) | ((uint32_t)__bfloat16_as_ushort(h1) << 16);
    lo = (uint32_t)__bfloat16_as_ushort(l0) | ((uint32_t)__bfloat16_as_ushort(l1) << 16);
}

// ======= Kernel 1: tgt_emb -> swizzled bf16 hi/lo blobs (SMEM image) + ytg =======
#define CV_PAD 264
#define CONVB_SMEM ((TM * CV_PAD + TM) * 4)

__global__ void __launch_bounds__(256)
convB_kernel(const float* __restrict__ tgt_emb, const float* __restrict__ tgt) {
    extern __shared__ float cs[];          // [TM][CV_PAD] transpose stage
    float* syy = cs + TM * CV_PAD;
    const int tid = threadIdx.x;
    const int b = blockIdx.y, mt = blockIdx.x, m0 = mt * TM;

    if (tid < TM) syy[tid] = 0.f;
    __syncthreads();

    const float* g = tgt_emb + (size_t)b * DD * MM + m0;
    for (int i = tid; i < DD * TM; i += 256) {
        int d = i >> 5, m = i & 31;
        cs[m * CV_PAD + d] = g[(size_t)d * MM + m];
    }
    __syncthreads();

    unsigned char* outh = g_B + (size_t)(b * NMT + mt) * B_BLOB;
    unsigned char* outl = outh + B_HALF;

    for (int i = tid; i < TM * 32; i += 256) {   // task = (m-row, 16B chunk kg)
        int m = i >> 5, kg = i & 31;
        const float* p = cs + m * CV_PAD + kg * 8;
        float4 v0 = *(const float4*)(p);
        float4 v1 = *(const float4*)(p + 4);
        float part = v0.x * v0.x + v0.y * v0.y + v0.z * v0.z + v0.w * v0.w
                   + v1.x * v1.x + v1.y * v1.y + v1.z * v1.z + v1.w * v1.w;
        atomicAdd(&syy[m], part);

        uint4 hq, lq;
        split_pair(v0.x, v0.y, hq.x, lq.x);
        split_pair(v0.z, v0.w, hq.y, lq.y);
        split_pair(v1.x, v1.y, hq.z, lq.z);
        split_pair(v1.z, v1.w, hq.w, lq.w);

        int byte = m * ROW_BYTES + ((kg ^ (m & 7)) << 4);  // XOR swizzle
        *(uint4*)(outh + byte) = hq;
        *(uint4*)(outl + byte) = lq;
    }
    __syncthreads();
    if (tid < TM) {
        int m = m0 + tid;
        float4 v;
        v.x = L2E * syy[tid];
        v.y = tgt[(size_t)b * 3 * MM + m];
        v.z = tgt[(size_t)b * 3 * MM + MM + m];
        v.w = tgt[(size_t)b * 3 * MM + 2 * MM + m];
        g_ytg[b * MM + m] = v;
    }
}

// ======= Kernel 2: fused HMMA GEMM, 3-stage ring, free-running warps =======
// SMEM: mbar full/empty x3 @0..47, ytg 3x512 @64, A @1664, B stages @132736
#define SM_YTG 64
#define SM_A   1664
#define SM_B   (SM_A + 2 * A_HALF)              // 132736
#define SMEM_MAIN (SM_B + NSTAGE * B_BLOB)      // 231040

struct RowState { float m, s, o0, o1, o2; };

__device__ __forceinline__ void row_update(RowState& st, const float (&lg)[8],
                                           const float4 (&yt)[8]) {
    float tmax = lg[0];
#pragma unroll
    for (int j = 1; j < 8; ++j) tmax = fmaxf(tmax, lg[j]);
    float nm = fmaxf(st.m, tmax);
    float corr = ex2(st.m - nm);
    st.m = nm;
    float ls = 0.f, a0 = 0.f, a1 = 0.f, a2 = 0.f;
#pragma unroll
    for (int j = 0; j < 8; ++j) {
        float p = ex2(lg[j] - nm);
        ls += p;
        a0 += p * yt[j].y;
        a1 += p * yt[j].z;
        a2 += p * yt[j].w;
    }
    st.s = st.s * corr + ls;
    st.o0 = st.o0 * corr + a0;
    st.o1 = st.o1 * corr + a1;
    st.o2 = st.o2 * corr + a2;
}

__device__ __forceinline__ void row_merge(RowState& st, int off) {
    float om = __shfl_xor_sync(0xffffffffu, st.m, off);
    float os = __shfl_xor_sync(0xffffffffu, st.s, off);
    float g0 = __shfl_xor_sync(0xffffffffu, st.o0, off);
    float g1 = __shfl_xor_sync(0xffffffffu, st.o1, off);
    float g2 = __shfl_xor_sync(0xffffffffu, st.o2, off);
    float nm = fmaxf(st.m, om);
    float ca = ex2(st.m - nm), cb = ex2(om - nm);
    st.m = nm;
    st.s = st.s * ca + os * cb;
    st.o0 = st.o0 * ca + g0 * cb;
    st.o1 = st.o1 * ca + g1 * cb;
    st.o2 = st.o2 * ca + g2 * cb;
}

__global__ void __launch_bounds__(256, 1)
corr_mma_kernel(const float* __restrict__ src_emb, float* __restrict__ out) {
    extern __shared__ __align__(16) unsigned char smraw[];
    const uint32_t sb = smem_u32(smraw);
    const int tid = threadIdx.x;
    const int wid = tid >> 5;
    const int lane = tid & 31;
    const int b = blockIdx.y;
    const int n0 = blockIdx.x * TN;

    if (tid == 0) {
#pragma unroll
        for (int s = 0; s < NSTAGE; ++s) {
            MBARRIER_INIT(sb + s * 16, 1);       // full
            MBARRIER_INIT(sb + s * 16 + 8, 8);   // empty: 8 warp arrivals
        }
    }
    __syncthreads();

    const unsigned char* gB = g_B + (size_t)b * NMT * B_BLOB;
    const float4* gY = g_ytg + b * MM;

    // kick off loads for tiles 0..2
    if (tid == 0) {
#pragma unroll
        for (int s = 0; s < NSTAGE; ++s) {
            MBARRIER_EXPECT_TX(sb + s * 16, B_BLOB + 512);
            bulk_g2s(sb + SM_B + s * B_BLOB, gB + (size_t)s * B_BLOB, B_BLOB, sb + s * 16);
            bulk_g2s(sb + SM_YTG + s * 512, gY + s * TM, 512, sb + s * 16);
        }
    }

    // ---- convert A (src_emb rows n0..n0+127, scaled by 2*log2e) into SMEM ----
    {
        unsigned char* Ah = smraw + SM_A;
        unsigned char* Al = Ah + A_HALF;
        const float* gA = src_emb + (size_t)b * DD * NN + n0;
        const float sc = 2.0f * L2E;
        for (int i = tid; i < DD * TN / 2; i += 256) {
            int n = i & 127;
            int dp = i >> 7;             // 0..127, covers d = 2dp, 2dp+1
            float v0 = sc * gA[(size_t)(2 * dp) * NN + n];
            float v1 = sc * gA[(size_t)(2 * dp + 1) * NN + n];
            uint32_t hi, lo;
            split_pair(v0, v1, hi, lo);
            int byte = n * ROW_BYTES + (((dp >> 2) ^ (n & 7)) << 4) + (dp & 3) * 4;
            *(uint32_t*)(Ah + byte) = hi;
            *(uint32_t*)(Al + byte) = lo;
        }
    }
    __syncthreads();

    // ---- ldmatrix per-lane bases (swizzled chunk addressing) ----
    const int q = lane & 3;
    const int r = lane >> 2;
    const uint32_t rowA = wid * 16 + ((lane >> 3) & 1) * 8 + (lane & 7);
    const uint32_t aBase = sb + SM_A + rowA * ROW_BYTES;
    const uint32_t hcA = (uint32_t)(lane >> 4);       // 0/1
    const uint32_t rswA = rowA & 7;
    const uint32_t rB0 = (uint32_t)((lane >> 4) * 8 + (lane & 7));  // rows 0..15
    const uint32_t bBase0 = rB0 * ROW_BYTES;
    const uint32_t hcB = (uint32_t)((lane >> 3) & 1);
    const uint32_t rswB = rB0 & 7;

    RowState st0 = {-1e30f, 0.f, 0.f, 0.f, 0.f};
    RowState st1 = {-1e30f, 0.f, 0.f, 0.f, 0.f};

    const float4* ytg_s = (const float4*)(smraw + SM_YTG);

    int stage = 0, phase = 0;
    for (int t = 0; t < NMT; ++t) {
        MBARRIER_WAIT_PARITY(sb + stage * 16, phase);

        const uint32_t bb = sb + SM_B + stage * B_BLOB;

        float acc[4][4];
#pragma unroll
        for (int j = 0; j < 4; ++j)
#pragma unroll
            for (int e = 0; e < 4; ++e) acc[j][e] = 0.f;

#pragma unroll
        for (int s = 0; s < 16; ++s) {
            const uint32_t swA = ((2 * s + hcA) ^ rswA) << 4;
            const uint32_t swB = ((2 * s + hcB) ^ rswB) << 4;
            uint32_t ah[4], al[4], bh[4], bh2[4], bl[4], bl2[4];
            LDSM_X4(ah, aBase + swA);
            LDSM_X4(al, aBase + swA + A_HALF);
            LDSM_X4(bh, bb + bBase0 + swB);
            LDSM_X4(bh2, bb + bBase0 + swB + 16 * ROW_BYTES);
            LDSM_X4(bl, bb + bBase0 + swB + B_HALF);
            LDSM_X4(bl2, bb + bBase0 + swB + B_HALF + 16 * ROW_BYTES);
            // hi*hi
            mma_bf16(acc[0], ah, bh[0], bh[1]);
            mma_bf16(acc[1], ah, bh[2], bh[3]);
            mma_bf16(acc[2], ah, bh2[0], bh2[1]);
            mma_bf16(acc[3], ah, bh2[2], bh2[3]);
            // lo*hi
            mma_bf16(acc[0], al, bh[0], bh[1]);
            mma_bf16(acc[1], al, bh[2], bh[3]);
            mma_bf16(acc[2], al, bh2[0], bh2[1]);
            mma_bf16(acc[3], al, bh2[2], bh2[3]);
            // hi*lo
            mma_bf16(acc[0], ah, bl[0], bl[1]);
            mma_bf16(acc[1], ah, bl[2], bl[3]);
            mma_bf16(acc[2], ah, bl2[0], bl2[1]);
            mma_bf16(acc[3], ah, bl2[2], bl2[3]);
        }

        // grab this tile's (yy, t0..t2) for my 8 cols before releasing the buffer
        float4 yt[8];
#pragma unroll
        for (int j = 0; j < 4; ++j)
#pragma unroll
            for (int e = 0; e < 2; ++e)
                yt[j * 2 + e] = ytg_s[stage * 32 + j * 8 + q * 2 + e];

        if (lane == 0) MBARRIER_ARRIVE(sb + stage * 16 + 8);  // this warp done with buffer

        // producer: refill this stage for tile t+3 once all warps released it
        if (tid == 0 && t + NSTAGE < NMT) {
            MBARRIER_WAIT_PARITY(sb + stage * 16 + 8, phase);
            MBARRIER_EXPECT_TX(sb + stage * 16, B_BLOB + 512);
            bulk_g2s(sb + SM_B + stage * B_BLOB, gB + (size_t)(t + NSTAGE) * B_BLOB,
                     B_BLOB, sb + stage * 16);
            bulk_g2s(sb + SM_YTG + stage * 512, gY + (t + NSTAGE) * TM, 512,
                     sb + stage * 16);
        }

        // ---- per-thread online softmax (rows r0 = wid*16+r, r1 = +8) ----
        float l0[8], l1[8];
#pragma unroll
        for (int j = 0; j < 4; ++j)
#pragma unroll
            for (int e = 0; e < 2; ++e) {
                float yy = yt[j * 2 + e].x;
                l0[j * 2 + e] = acc[j][e] - yy;
                l1[j * 2 + e] = acc[j][2 + e] - yy;
            }
        row_update(st0, l0, yt);
        row_update(st1, l1, yt);

        if (++stage == NSTAGE) { stage = 0; phase ^= 1; }
    }

    // ---- merge across quad (lanes sharing the same rows), write out ----
    row_merge(st0, 1); row_merge(st0, 2);
    row_merge(st1, 1); row_merge(st1, 2);

    if (q == 0) {
        size_t base = (size_t)b * 3 * NN;
        int na = n0 + wid * 16 + r;
        int nb = na + 8;
        float ia = 1.f / st0.s, ib = 1.f / st1.s;
        out[base + na] = st0.o0 * ia;
        out[base + NN + na] = st0.o1 * ia;
        out[base + 2 * NN + na] = st0.o2 * ia;
        out[base + nb] = st1.o0 * ib;
        out[base + NN + nb] = st1.o1 * ib;
        out[base + 2 * NN + nb] = st1.o2 * ib;
    }
}

extern "C" void kernel_launch(void* const* d_in, const int* in_sizes, int n_in,
                              void* d_out, int out_size) {
    // inputs per metadata: [0]=src (unused), [1]=tgt, [2]=src_emb, [3]=tgt_emb
    const float* tgt     = (const float*)d_in[1];
    const float* src_emb = (const float*)d_in[2];
    const float* tgt_emb = (const float*)d_in[3];
    float* out = (float*)d_out;

    cudaFuncSetAttribute(convB_kernel,
                         cudaFuncAttributeMaxDynamicSharedMemorySize, CONVB_SMEM);
    cudaFuncSetAttribute(corr_mma_kernel,
                         cudaFuncAttributeMaxDynamicSharedMemorySize, SMEM_MAIN);

    convB_kernel<<<dim3(NMT, BB), 256, CONVB_SMEM>>>(tgt_emb, tgt);
    corr_mma_kernel<<<dim3(NN / TN, BB), 256, SMEM_MAIN>>>(src_emb, out);
}